// round 1
// baseline (speedup 1.0000x reference)
#include <cuda_runtime.h>
#include <cuda_bf16.h>

// ============================================================================
// CrossAttention collapses algebraically:
//   scores = softmax(qk) sums to exactly L=2048 over (q,k) per (b,h), and the
//   einsum 'bvhd,bhqk->bvhd' has no shared contraction index, so
//     attn = v * 2048
//     out  = 2048 * (x@Wv + bv) @ Wo + bo
//          = 2048 * x @ (Wv@Wo) + (2048 * bv@Wo + bo)
//   -> one 1024^3 GEMM (Wc), one tiny bias vector, one 8192x1024x1024 GEMM.
//   encoder_x / Wq / Wk / biases q,k are dead inputs.
// ============================================================================

#define BM 128
#define BN 128
#define BK 8
#define TM 8
#define TN 8
#define NTHREADS 256

// Scratch (no cudaMalloc allowed)
__device__ float g_Wc[1024 * 1024];   // Wv @ Wo
__device__ float g_t[1024];           // 2048*bv@Wo + bo

// ----------------------------------------------------------------------------
// Tiled fp32 SGEMM: C = alpha * A[MxK] @ B[KxN] + (bias ? bias[n] : 0)
// Requires M % 128 == 0, N % 128 == 0, K % 8 == 0 (true for all our shapes).
// ----------------------------------------------------------------------------
__global__ __launch_bounds__(NTHREADS, 2)
void sgemm_kernel(const float* __restrict__ A, const float* __restrict__ B,
                  float* __restrict__ C, const float* __restrict__ bias,
                  int M, int N, int K, float alpha)
{
    __shared__ float As[BK][BM];
    __shared__ float Bs[BK][BN];

    const int tid = threadIdx.x;
    const int bm  = blockIdx.y;
    const int bn  = blockIdx.x;

    // A-tile load map: 128 rows x 8 cols = 256 float4 -> 1 per thread
    const int arow  = tid >> 1;          // 0..127
    const int acol4 = (tid & 1) * 4;     // 0 or 4
    // B-tile load map: 8 rows x 128 cols = 256 float4 -> 1 per thread
    const int brow  = tid >> 5;          // 0..7
    const int bcol4 = (tid & 31) * 4;    // 0,4,...,124

    const int ty = tid >> 4;             // 0..15 -> row group
    const int tx = tid & 15;             // 0..15 -> col group

    const float* Ab = A + (size_t)(bm * BM) * K;
    const float* Bb = B + bn * BN;

    float acc[TM][TN];
    #pragma unroll
    for (int i = 0; i < TM; i++)
        #pragma unroll
        for (int j = 0; j < TN; j++) acc[i][j] = 0.0f;

    for (int k0 = 0; k0 < K; k0 += BK) {
        // load A tile (transposed into smem: As[k][m])
        float4 av = *(const float4*)(Ab + (size_t)arow * K + k0 + acol4);
        As[acol4 + 0][arow] = av.x;
        As[acol4 + 1][arow] = av.y;
        As[acol4 + 2][arow] = av.z;
        As[acol4 + 3][arow] = av.w;
        // load B tile (row-major: Bs[k][n])
        *(float4*)&Bs[brow][bcol4] =
            *(const float4*)(Bb + (size_t)(k0 + brow) * N + bcol4);
        __syncthreads();

        #pragma unroll
        for (int kk = 0; kk < BK; kk++) {
            float a[TM], b[TN];
            #pragma unroll
            for (int i = 0; i < TM; i++) a[i] = As[kk][ty * TM + i];
            #pragma unroll
            for (int j = 0; j < TN; j++) b[j] = Bs[kk][tx * TN + j];
            #pragma unroll
            for (int i = 0; i < TM; i++)
                #pragma unroll
                for (int j = 0; j < TN; j++)
                    acc[i][j] = fmaf(a[i], b[j], acc[i][j]);
        }
        __syncthreads();
    }

    // epilogue: alpha-scale + per-column bias, vectorized stores
    const int col0 = bn * BN + tx * TN;
    #pragma unroll
    for (int i = 0; i < TM; i++) {
        const size_t row = (size_t)(bm * BM + ty * TM + i);
        float* Cp = C + row * N + col0;
        #pragma unroll
        for (int j = 0; j < TN; j += 4) {
            float4 r;
            r.x = alpha * acc[i][j + 0];
            r.y = alpha * acc[i][j + 1];
            r.z = alpha * acc[i][j + 2];
            r.w = alpha * acc[i][j + 3];
            if (bias) {
                r.x += bias[col0 + j + 0];
                r.y += bias[col0 + j + 1];
                r.z += bias[col0 + j + 2];
                r.w += bias[col0 + j + 3];
            }
            *(float4*)(Cp + j) = r;
        }
    }
}

// ----------------------------------------------------------------------------
// t[j] = 2048 * sum_i bv[i] * Wo[i,j] + bo[j]
// ----------------------------------------------------------------------------
__global__ void bias_kernel(const float* __restrict__ bv,
                            const float* __restrict__ Wo,
                            const float* __restrict__ bo,
                            float* __restrict__ t,
                            int K, int N, float alpha)
{
    int j = blockIdx.x * blockDim.x + threadIdx.x;
    if (j < N) {
        float s = 0.0f;
        for (int i = 0; i < K; i++)
            s = fmaf(bv[i], Wo[(size_t)i * N + j], s);
        t[j] = alpha * s + bo[j];
    }
}

// ----------------------------------------------------------------------------
extern "C" void kernel_launch(void* const* d_in, const int* in_sizes, int n_in,
                              void* d_out, int out_size)
{
    const float* x  = (const float*)d_in[0];
    // d_in[1..5] = encoder_x, Wq, bq, Wk, bk  -- mathematically dead
    const float* Wv = (const float*)d_in[6];
    const float* bv = (const float*)d_in[7];
    const float* Wo = (const float*)d_in[8];
    const float* bo = (const float*)d_in[9];
    float* out = (float*)d_out;

    const int B = 4, L = 2048, D = 1024;
    const int M = B * L;       // 8192
    const float Lf = (float)L; // 2048

    float* wc = nullptr;
    float* t  = nullptr;
    cudaGetSymbolAddress((void**)&wc, g_Wc);
    cudaGetSymbolAddress((void**)&t,  g_t);

    // 1) bias vector t = 2048*bv@Wo + bo
    bias_kernel<<<(D + 255) / 256, 256>>>(bv, Wo, bo, t, D, D, Lf);

    // 2) Wc = Wv @ Wo  (1024x1024x1024)
    {
        dim3 grid(D / BN, D / BM);
        sgemm_kernel<<<grid, NTHREADS>>>(Wv, Wo, wc, nullptr, D, D, D, 1.0f);
    }

    // 3) out = 2048 * x @ Wc + t  (8192x1024x1024)
    {
        dim3 grid(D / BN, M / BM);
        sgemm_kernel<<<grid, NTHREADS>>>(x, wc, out, t, M, D, D, Lf);
    }
}

// round 3
// speedup vs baseline: 2.8150x; 2.8150x over previous
#include <cuda_runtime.h>
#include <cuda_bf16.h>
#include <stdint.h>

// ============================================================================
// CrossAttention collapses algebraically:
//   softmax over k sums to 1 per query -> sum over (q,k) of scores = L = 2048.
//   einsum 'bvhd,bhqk->bvhd' has no shared contraction index, so attn = v*2048:
//     out = 2048 * x @ (Wv@Wo) + (2048 * bv@Wo + bo)
// encoder_x / Wq / bq / Wk / bk are dead inputs.
//
// GEMMs via legacy HMMA mma.sync (tcgen05 PTX is rejected: harness targets
// sm_103 without the 'a' feature suffix). Precision via split-bf16 3-pass:
//   A@B ~= Ah@Bh + Ah@Bl + Al@Bh  (fp32 accum in registers, lo*lo dropped)
// ============================================================================

// ---------------- scratch (__device__ globals; no cudaMalloc allowed) -------
__device__ __nv_bfloat16 g_xh [8192u * 1024u];
__device__ __nv_bfloat16 g_xl [8192u * 1024u];
__device__ __nv_bfloat16 g_Wvh[1024u * 1024u];
__device__ __nv_bfloat16 g_Wvl[1024u * 1024u];
__device__ __nv_bfloat16 g_WoTh[1024u * 1024u];
__device__ __nv_bfloat16 g_WoTl[1024u * 1024u];
__device__ __nv_bfloat16 g_WcTh[1024u * 1024u];
__device__ __nv_bfloat16 g_WcTl[1024u * 1024u];
__device__ float g_Wc[1024u * 1024u];
__device__ float g_part[16 * 1024];
__device__ float g_t[1024];

// ---------------- helpers ---------------------------------------------------
__device__ __forceinline__ uint32_t smem_u32(const void* p) {
    uint32_t a;
    asm("{ .reg .u64 t; cvta.to.shared.u64 t, %1; cvt.u32.u64 %0, t; }"
        : "=r"(a) : "l"(p));
    return a;
}

__device__ __forceinline__ void cp_async16(uint32_t saddr, const void* gaddr) {
    asm volatile("cp.async.cg.shared.global [%0], [%1], 16;"
                 :: "r"(saddr), "l"(gaddr));
}
#define CP_COMMIT() asm volatile("cp.async.commit_group;" ::: "memory")
#define CP_WAIT0()  asm volatile("cp.async.wait_group 0;" ::: "memory")

// m16n8k16 bf16 MMA, fp32 accumulate (sm_80+ feature; valid on plain sm_103)
__device__ __forceinline__ void mma16816(float* c, const uint32_t* a,
                                         const uint32_t* b) {
    asm volatile(
        "mma.sync.aligned.m16n8k16.row.col.f32.bf16.bf16.f32 "
        "{%0,%1,%2,%3}, {%4,%5,%6,%7}, {%8,%9}, {%0,%1,%2,%3};"
        : "+f"(c[0]), "+f"(c[1]), "+f"(c[2]), "+f"(c[3])
        : "r"(a[0]), "r"(a[1]), "r"(a[2]), "r"(a[3]), "r"(b[0]), "r"(b[1]));
}

// swizzled 32-bit smem read from a 128-byte-row K-major tile
__device__ __forceinline__ uint32_t lds32(const char* base, int row, int kb) {
    uint32_t so = (uint32_t)(row * 128 + kb);
    so ^= (so >> 3) & 0x70;
    return *(const uint32_t*)(base + so);
}

// ---------------- split-bf16 HMMA GEMM --------------------------------------
// C[M,N] = alpha*(A@B) + bias[n].  A hi/lo: [M,K] K-major bf16.
// B hi/lo: [N,K] K-major bf16 (i.e. B-transposed storage).
// M,N multiples of 128; K multiple of 64.
#define GT 256
#define TILE_B 16384u            // 128 rows x 128 bytes (128x64 bf16)
#define STAGE  (4u * TILE_B)     // Ah | Al | Bh | Bl
#define SMEM_BYTES (2u * STAGE)  // double buffered = 131072

__global__ __launch_bounds__(GT, 1)
void gemm_hmma(const __nv_bfloat16* __restrict__ Ah,
               const __nv_bfloat16* __restrict__ Al,
               const __nv_bfloat16* __restrict__ Bh,
               const __nv_bfloat16* __restrict__ Bl,
               float* __restrict__ C, const float* __restrict__ bias,
               int M, int N, int K, float alpha)
{
    extern __shared__ char smem[];
    const uint32_t sb = smem_u32(smem);
    const int tid = threadIdx.x;
    const int wid = tid >> 5, lane = tid & 31;
    const int g = lane >> 2, tig = lane & 3;
    const int bm = blockIdx.y, bn = blockIdx.x;
    const int wm = (wid >> 2) * 64;   // warp m-origin (2 warps in m)
    const int wn = (wid & 3) * 32;    // warp n-origin (4 warps in n)

    const __nv_bfloat16* src[4] = {
        Ah + (size_t)bm * 128 * K, Al + (size_t)bm * 128 * K,
        Bh + (size_t)bn * 128 * K, Bl + (size_t)bn * 128 * K };

    float acc[4][4][4];
    #pragma unroll
    for (int mt = 0; mt < 4; mt++)
        #pragma unroll
        for (int nt = 0; nt < 4; nt++)
            #pragma unroll
            for (int i = 0; i < 4; i++) acc[mt][nt][i] = 0.0f;

    const int nch = K / 64;

    // ---- async tile loader: chunk c -> stage (c&1)
    auto issue = [&](int c) {
        const int k0 = c * 64;
        const uint32_t stg = sb + (uint32_t)(c & 1) * STAGE;
        #pragma unroll
        for (int t = 0; t < 4; t++) {
            const __nv_bfloat16* s = src[t] + k0;
            const uint32_t tb = stg + t * TILE_B;
            #pragma unroll
            for (int i = 0; i < 4; i++) {
                const int li = i * GT + tid;
                const int row = li >> 3, kc = li & 7;
                uint32_t so = (uint32_t)(row * 128 + kc * 16);
                so ^= (so >> 3) & 0x70;
                cp_async16(tb + so, s + (size_t)row * K + kc * 8);
            }
        }
        CP_COMMIT();
    };

    issue(0);

    for (int c = 0; c < nch; c++) {
        CP_WAIT0();
        __syncthreads();
        if (c + 1 < nch) issue(c + 1);

        const char* stg = smem + (size_t)(c & 1) * STAGE;
        const int pa[3] = {0, 0, 1}, pb[3] = {2, 3, 2};
        #pragma unroll
        for (int p = 0; p < 3; p++) {
            const char* Abuf = stg + pa[p] * TILE_B;
            const char* Bbuf = stg + pb[p] * TILE_B;
            #pragma unroll
            for (int ks = 0; ks < 4; ks++) {
                const int kb = ks * 32 + tig * 4;   // byte offset of k=ks*16+tig*2
                uint32_t a[4][4], b[4][2];
                #pragma unroll
                for (int mt = 0; mt < 4; mt++) {
                    const int r0 = wm + mt * 16 + g;
                    a[mt][0] = lds32(Abuf, r0,     kb);
                    a[mt][1] = lds32(Abuf, r0 + 8, kb);
                    a[mt][2] = lds32(Abuf, r0,     kb + 16);
                    a[mt][3] = lds32(Abuf, r0 + 8, kb + 16);
                }
                #pragma unroll
                for (int nt = 0; nt < 4; nt++) {
                    const int nr = wn + nt * 8 + g;
                    b[nt][0] = lds32(Bbuf, nr, kb);
                    b[nt][1] = lds32(Bbuf, nr, kb + 16);
                }
                #pragma unroll
                for (int mt = 0; mt < 4; mt++)
                    #pragma unroll
                    for (int nt = 0; nt < 4; nt++)
                        mma16816(acc[mt][nt], a[mt], b[nt]);
            }
        }
        __syncthreads();
    }

    // ---- epilogue: direct float2 stores
    #pragma unroll
    for (int mt = 0; mt < 4; mt++) {
        const size_t r0 = (size_t)bm * 128 + wm + mt * 16 + g;
        #pragma unroll
        for (int nt = 0; nt < 4; nt++) {
            const int c0 = bn * 128 + wn + nt * 8 + tig * 2;
            float bx = 0.f, by = 0.f;
            if (bias) { bx = bias[c0]; by = bias[c0 + 1]; }
            float2 v0 = { alpha * acc[mt][nt][0] + bx,
                          alpha * acc[mt][nt][1] + by };
            float2 v1 = { alpha * acc[mt][nt][2] + bx,
                          alpha * acc[mt][nt][3] + by };
            *(float2*)(C + r0 * N + c0)       = v0;
            *(float2*)(C + (r0 + 8) * N + c0) = v1;
        }
    }
}

// ---------------- fp32 -> bf16 hi/lo, row-major ----------------------------
__global__ void split_rm(const float* __restrict__ src,
                         __nv_bfloat16* __restrict__ hi,
                         __nv_bfloat16* __restrict__ lo, int n4)
{
    const int i = blockIdx.x * blockDim.x + threadIdx.x;
    if (i < n4) {
        const float4 v = ((const float4*)src)[i];
        __nv_bfloat16 h0 = __float2bfloat16(v.x), h1 = __float2bfloat16(v.y);
        __nv_bfloat16 h2 = __float2bfloat16(v.z), h3 = __float2bfloat16(v.w);
        __nv_bfloat16 l0 = __float2bfloat16(v.x - __bfloat162float(h0));
        __nv_bfloat16 l1 = __float2bfloat16(v.y - __bfloat162float(h1));
        __nv_bfloat16 l2 = __float2bfloat16(v.z - __bfloat162float(h2));
        __nv_bfloat16 l3 = __float2bfloat16(v.w - __bfloat162float(h3));
        ((__nv_bfloat162*)hi)[2 * i]     = __halves2bfloat162(h0, h1);
        ((__nv_bfloat162*)hi)[2 * i + 1] = __halves2bfloat162(h2, h3);
        ((__nv_bfloat162*)lo)[2 * i]     = __halves2bfloat162(l0, l1);
        ((__nv_bfloat162*)lo)[2 * i + 1] = __halves2bfloat162(l2, l3);
    }
}

// ---------------- fp32 [R,C] -> bf16 hi/lo transposed [C,R] ----------------
__global__ void split_tr(const float* __restrict__ W,
                         __nv_bfloat16* __restrict__ Th,
                         __nv_bfloat16* __restrict__ Tl, int R, int C)
{
    __shared__ float t[32][33];
    const int bx = blockIdx.x, by = blockIdx.y;
    const int tx = threadIdx.x, ty = threadIdx.y;   // 32 x 8
    #pragma unroll
    for (int i = 0; i < 32; i += 8)
        t[ty + i][tx] = W[(size_t)(by * 32 + ty + i) * C + bx * 32 + tx];
    __syncthreads();
    #pragma unroll
    for (int i = 0; i < 32; i += 8) {
        const float v = t[tx][ty + i];
        const __nv_bfloat16 h = __float2bfloat16(v);
        const __nv_bfloat16 l = __float2bfloat16(v - __bfloat162float(h));
        const size_t o = (size_t)(bx * 32 + ty + i) * R + by * 32 + tx;
        Th[o] = h;
        Tl[o] = l;
    }
}

// ---------------- bias: t = 2048 * bv @ Wo + bo ----------------------------
__global__ void bias_partial(const float* __restrict__ bv,
                             const float* __restrict__ Wo)
{
    const int j = blockIdx.x * 128 + threadIdx.x;
    const int i0 = blockIdx.y * 64;
    float s = 0.0f;
    #pragma unroll 8
    for (int i = 0; i < 64; i++)
        s = fmaf(bv[i0 + i], Wo[(size_t)(i0 + i) * 1024 + j], s);
    g_part[blockIdx.y * 1024 + j] = s;
}

__global__ void bias_final(const float* __restrict__ bo)
{
    const int j = blockIdx.x * 128 + threadIdx.x;
    float s = 0.0f;
    #pragma unroll
    for (int p = 0; p < 16; p++) s += g_part[p * 1024 + j];
    g_t[j] = 2048.0f * s + bo[j];
}

// ---------------------------------------------------------------------------
extern "C" void kernel_launch(void* const* d_in, const int* in_sizes, int n_in,
                              void* d_out, int out_size)
{
    const float* x  = (const float*)d_in[0];
    // d_in[1..5] = encoder_x, Wq, bq, Wk, bk -- mathematically dead
    const float* Wv = (const float*)d_in[6];
    const float* bv = (const float*)d_in[7];
    const float* Wo = (const float*)d_in[8];
    const float* bo = (const float*)d_in[9];
    float* out = (float*)d_out;

    const int D = 1024, M = 8192;

    __nv_bfloat16 *xh, *xl, *Wvh, *Wvl, *WoTh, *WoTl, *WcTh, *WcTl;
    float *Wc, *t;
    cudaGetSymbolAddress((void**)&xh,   g_xh);
    cudaGetSymbolAddress((void**)&xl,   g_xl);
    cudaGetSymbolAddress((void**)&Wvh,  g_Wvh);
    cudaGetSymbolAddress((void**)&Wvl,  g_Wvl);
    cudaGetSymbolAddress((void**)&WoTh, g_WoTh);
    cudaGetSymbolAddress((void**)&WoTl, g_WoTl);
    cudaGetSymbolAddress((void**)&WcTh, g_WcTh);
    cudaGetSymbolAddress((void**)&WcTl, g_WcTl);
    cudaGetSymbolAddress((void**)&Wc,   g_Wc);
    cudaGetSymbolAddress((void**)&t,    g_t);

    static int smem_set = 0;
    if (!smem_set) {
        cudaFuncSetAttribute(gemm_hmma,
                             cudaFuncAttributeMaxDynamicSharedMemorySize,
                             SMEM_BYTES);
        smem_set = 1;
    }

    // conversions
    split_rm<<<(M * D / 4) / 256, 256>>>(x, xh, xl, M * D / 4);
    split_rm<<<(D * D / 4) / 256, 256>>>(Wv, Wvh, Wvl, D * D / 4);
    {
        dim3 g(D / 32, D / 32), b(32, 8);
        split_tr<<<g, b>>>(Wo, WoTh, WoTl, D, D);
    }

    // bias t = 2048*bv@Wo + bo
    {
        dim3 g(8, 16);
        bias_partial<<<g, 128>>>(bv, Wo);
        bias_final<<<8, 128>>>(bo);
    }

    // Wc = Wv @ Wo  (1024^3)
    {
        dim3 g(D / 128, D / 128);
        gemm_hmma<<<g, GT, SMEM_BYTES>>>(Wvh, Wvl, WoTh, WoTl, Wc, nullptr,
                                         D, D, D, 1.0f);
    }
    {
        dim3 g(D / 32, D / 32), b(32, 8);
        split_tr<<<g, b>>>(Wc, WcTh, WcTl, D, D);
    }

    // out = 2048 * x @ Wc + t  (8192 x 1024 x 1024)
    {
        dim3 g(D / 128, M / 128);
        gemm_hmma<<<g, GT, SMEM_BYTES>>>(xh, xl, WcTh, WcTl, out, t,
                                         M, D, D, 2048.0f);
    }
}

// round 4
// speedup vs baseline: 2.8415x; 1.0094x over previous
#include <cuda_runtime.h>
#include <cuda_bf16.h>
#include <stdint.h>

// ============================================================================
// CrossAttention collapses algebraically:
//   softmax over k sums to 1 per query -> sum over (q,k) of scores = L = 2048.
//   einsum 'bvhd,bhqk->bvhd' has no shared contraction index, so attn = v*2048:
//     out = 2048 * x @ (Wv@Wo) + (2048 * bv@Wo + bo)
// encoder_x / Wq / bq / Wk / bk are dead inputs.
//
// GEMMs via legacy HMMA mma.sync (tcgen05 PTX rejected: harness targets sm_103
// without 'a'). split-bf16 3-pass: A@B ~= Ah@Bh + Ah@Bl + Al@Bh (fp32 accum).
// R4: 64x64 warp tiles + ldmatrix.x4 + 128x256 CTA (85B smem/MMA vs 192B).
// ============================================================================

// ---------------- scratch ----------------------------------------------------
__device__ __nv_bfloat16 g_xh [8192u * 1024u];
__device__ __nv_bfloat16 g_xl [8192u * 1024u];
__device__ __nv_bfloat16 g_Wvh[1024u * 1024u];
__device__ __nv_bfloat16 g_Wvl[1024u * 1024u];
__device__ __nv_bfloat16 g_WoTh[1024u * 1024u];
__device__ __nv_bfloat16 g_WoTl[1024u * 1024u];
__device__ __nv_bfloat16 g_WcTh[1024u * 1024u];
__device__ __nv_bfloat16 g_WcTl[1024u * 1024u];
__device__ float g_Wc[1024u * 1024u];
__device__ float g_part[64 * 1024];
__device__ float g_t[1024];

// ---------------- helpers ----------------------------------------------------
__device__ __forceinline__ uint32_t smem_u32(const void* p) {
    uint32_t a;
    asm("{ .reg .u64 t; cvta.to.shared.u64 t, %1; cvt.u32.u64 %0, t; }"
        : "=r"(a) : "l"(p));
    return a;
}
__device__ __forceinline__ void cp_async16(uint32_t saddr, const void* gaddr) {
    asm volatile("cp.async.cg.shared.global [%0], [%1], 16;"
                 :: "r"(saddr), "l"(gaddr));
}
#define CP_COMMIT() asm volatile("cp.async.commit_group;" ::: "memory")
#define CP_WAIT0()  asm volatile("cp.async.wait_group 0;" ::: "memory")

__device__ __forceinline__ void mma16816(float* c, const uint32_t* a,
                                         const uint32_t* b) {
    asm volatile(
        "mma.sync.aligned.m16n8k16.row.col.f32.bf16.bf16.f32 "
        "{%0,%1,%2,%3}, {%4,%5,%6,%7}, {%8,%9}, {%0,%1,%2,%3};"
        : "+f"(c[0]), "+f"(c[1]), "+f"(c[2]), "+f"(c[3])
        : "r"(a[0]), "r"(a[1]), "r"(a[2]), "r"(a[3]), "r"(b[0]), "r"(b[1]));
}
__device__ __forceinline__ void ldsm4(uint32_t* r, uint32_t addr) {
    asm volatile("ldmatrix.sync.aligned.m8n8.x4.shared.b16 {%0,%1,%2,%3}, [%4];"
                 : "=r"(r[0]), "=r"(r[1]), "=r"(r[2]), "=r"(r[3]) : "r"(addr));
}
// swizzled offset inside a 128B-row tile (row<512, col<128):
// swz(row*128+col) = row*128 + (col ^ ((row&7)<<4))
__device__ __forceinline__ uint32_t swz(int row, int col) {
    return (uint32_t)(row * 128 + (col ^ ((row & 7) << 4)));
}

// ---------------- split-bf16 HMMA GEMM --------------------------------------
// C[M,N] = alpha*(A@B) + bias[n].  A hi/lo: [M,K] K-major bf16.
// B hi/lo: [N,K] K-major bf16.  M%128==0, N%256==0, K%64==0.
#define GT 256
#define TA_B 16384u              // A tile: 128 x 128B
#define TB_B 32768u              // B tile: 256 x 128B
#define STAGE (2u * TA_B + 2u * TB_B)            // Ah|Al|Bh|Bl = 96KB
#define SMEM_BYTES (2u * STAGE)                   // 192KB

__global__ __launch_bounds__(GT, 1)
void gemm_hmma(const __nv_bfloat16* __restrict__ Ah,
               const __nv_bfloat16* __restrict__ Al,
               const __nv_bfloat16* __restrict__ Bh,
               const __nv_bfloat16* __restrict__ Bl,
               float* __restrict__ C, const float* __restrict__ bias,
               int M, int N, int K, float alpha)
{
    extern __shared__ char smem[];
    const uint32_t sb = smem_u32(smem);
    const int tid = threadIdx.x;
    const int wid = tid >> 5, lane = tid & 31;
    const int g = lane >> 2, tig = lane & 3;
    const int bm = blockIdx.y, bn = blockIdx.x;
    const int wm = (wid & 1) * 64;      // 2 warps over M
    const int wn = (wid >> 1) * 64;     // 4 warps over N

    // ldmatrix lane decomposition
    const int lm = lane >> 3;           // matrix index 0..3
    const int lr = lane & 7;            // row within 8x8 matrix

    const __nv_bfloat16* srcA[2] = { Ah + (size_t)bm * 128 * K,
                                     Al + (size_t)bm * 128 * K };
    const __nv_bfloat16* srcB[2] = { Bh + (size_t)bn * 256 * K,
                                     Bl + (size_t)bn * 256 * K };

    float acc[4][8][4];
    #pragma unroll
    for (int mt = 0; mt < 4; mt++)
        #pragma unroll
        for (int nt = 0; nt < 8; nt++)
            #pragma unroll
            for (int i = 0; i < 4; i++) acc[mt][nt][i] = 0.0f;

    const int nch = K / 64;

    auto issue = [&](int c) {
        const int k0 = c * 64;
        const uint32_t stg = sb + (uint32_t)(c & 1) * STAGE;
        #pragma unroll
        for (int t = 0; t < 2; t++) {               // A hi/lo: 4 iters each
            const __nv_bfloat16* s = srcA[t] + k0;
            const uint32_t tb = stg + t * TA_B;
            #pragma unroll
            for (int i = 0; i < 4; i++) {
                const int li = i * GT + tid;
                const int row = li >> 3, kc = li & 7;
                cp_async16(tb + swz(row, kc * 16), s + (size_t)row * K + kc * 8);
            }
        }
        #pragma unroll
        for (int t = 0; t < 2; t++) {               // B hi/lo: 8 iters each
            const __nv_bfloat16* s = srcB[t] + k0;
            const uint32_t tb = stg + 2 * TA_B + t * TB_B;
            #pragma unroll
            for (int i = 0; i < 8; i++) {
                const int li = i * GT + tid;
                const int row = li >> 3, kc = li & 7;
                cp_async16(tb + swz(row, kc * 16), s + (size_t)row * K + kc * 8);
            }
        }
        CP_COMMIT();
    };

    issue(0);

    for (int c = 0; c < nch; c++) {
        CP_WAIT0();
        __syncthreads();
        if (c + 1 < nch) issue(c + 1);

        const uint32_t stg = sb + (uint32_t)(c & 1) * STAGE;
        const uint32_t tAh = stg, tAl = stg + TA_B;
        const uint32_t tBh = stg + 2 * TA_B, tBl = stg + 2 * TA_B + TB_B;

        #pragma unroll
        for (int ks = 0; ks < 4; ks++) {
            const int kb = ks * 32;
            uint32_t aH[4][4], bH[4][4], bL[4][4];

            // Ah fragments: matrix m -> (row + (m&1)*8, col kb + (m>>1)*16)
            #pragma unroll
            for (int mt = 0; mt < 4; mt++) {
                const int row = wm + mt * 16 + (lm & 1) * 8 + lr;
                ldsm4(aH[mt], tAh + swz(row, kb + (lm >> 1) * 16));
            }
            // Bh fragments: matrix m -> nt = 2*nt2 + (m>>1), col kb + (m&1)*16
            #pragma unroll
            for (int nt2 = 0; nt2 < 4; nt2++) {
                const int row = wn + (2 * nt2 + (lm >> 1)) * 8 + lr;
                ldsm4(bH[nt2], tBh + swz(row, kb + (lm & 1) * 16));
            }
            // pass 1: Ah @ Bh
            #pragma unroll
            for (int mt = 0; mt < 4; mt++)
                #pragma unroll
                for (int nt2 = 0; nt2 < 4; nt2++) {
                    mma16816(acc[mt][2 * nt2],     aH[mt], &bH[nt2][0]);
                    mma16816(acc[mt][2 * nt2 + 1], aH[mt], &bH[nt2][2]);
                }
            // Bl fragments
            #pragma unroll
            for (int nt2 = 0; nt2 < 4; nt2++) {
                const int row = wn + (2 * nt2 + (lm >> 1)) * 8 + lr;
                ldsm4(bL[nt2], tBl + swz(row, kb + (lm & 1) * 16));
            }
            // pass 2: Ah @ Bl
            #pragma unroll
            for (int mt = 0; mt < 4; mt++)
                #pragma unroll
                for (int nt2 = 0; nt2 < 4; nt2++) {
                    mma16816(acc[mt][2 * nt2],     aH[mt], &bL[nt2][0]);
                    mma16816(acc[mt][2 * nt2 + 1], aH[mt], &bL[nt2][2]);
                }
            // Al fragments (overwrite aH)
            #pragma unroll
            for (int mt = 0; mt < 4; mt++) {
                const int row = wm + mt * 16 + (lm & 1) * 8 + lr;
                ldsm4(aH[mt], tAl + swz(row, kb + (lm >> 1) * 16));
            }
            // pass 3: Al @ Bh
            #pragma unroll
            for (int mt = 0; mt < 4; mt++)
                #pragma unroll
                for (int nt2 = 0; nt2 < 4; nt2++) {
                    mma16816(acc[mt][2 * nt2],     aH[mt], &bH[nt2][0]);
                    mma16816(acc[mt][2 * nt2 + 1], aH[mt], &bH[nt2][2]);
                }
        }
        __syncthreads();
    }

    // ---- epilogue: alpha + bias, float2 stores
    #pragma unroll
    for (int mt = 0; mt < 4; mt++) {
        const size_t r0 = (size_t)bm * 128 + wm + mt * 16 + g;
        #pragma unroll
        for (int nt = 0; nt < 8; nt++) {
            const int c0 = bn * 256 + wn + nt * 8 + tig * 2;
            float bx = 0.f, by = 0.f;
            if (bias) { bx = bias[c0]; by = bias[c0 + 1]; }
            float2 v0 = { alpha * acc[mt][nt][0] + bx,
                          alpha * acc[mt][nt][1] + by };
            float2 v1 = { alpha * acc[mt][nt][2] + bx,
                          alpha * acc[mt][nt][3] + by };
            *(float2*)(C + r0 * N + c0)       = v0;
            *(float2*)(C + (r0 + 8) * N + c0) = v1;
        }
    }
}

// ---------------- fp32 -> bf16 hi/lo, row-major ----------------------------
__global__ void split_rm(const float* __restrict__ src,
                         __nv_bfloat16* __restrict__ hi,
                         __nv_bfloat16* __restrict__ lo, int n4)
{
    const int i = blockIdx.x * blockDim.x + threadIdx.x;
    if (i < n4) {
        const float4 v = ((const float4*)src)[i];
        __nv_bfloat16 h0 = __float2bfloat16(v.x), h1 = __float2bfloat16(v.y);
        __nv_bfloat16 h2 = __float2bfloat16(v.z), h3 = __float2bfloat16(v.w);
        __nv_bfloat16 l0 = __float2bfloat16(v.x - __bfloat162float(h0));
        __nv_bfloat16 l1 = __float2bfloat16(v.y - __bfloat162float(h1));
        __nv_bfloat16 l2 = __float2bfloat16(v.z - __bfloat162float(h2));
        __nv_bfloat16 l3 = __float2bfloat16(v.w - __bfloat162float(h3));
        ((__nv_bfloat162*)hi)[2 * i]     = __halves2bfloat162(h0, h1);
        ((__nv_bfloat162*)hi)[2 * i + 1] = __halves2bfloat162(h2, h3);
        ((__nv_bfloat162*)lo)[2 * i]     = __halves2bfloat162(l0, l1);
        ((__nv_bfloat162*)lo)[2 * i + 1] = __halves2bfloat162(l2, l3);
    }
}

// ---------------- fp32 [R,C] -> bf16 hi/lo transposed [C,R] ----------------
__global__ void split_tr(const float* __restrict__ W,
                         __nv_bfloat16* __restrict__ Th,
                         __nv_bfloat16* __restrict__ Tl, int R, int C)
{
    __shared__ float t[32][33];
    const int bx = blockIdx.x, by = blockIdx.y;
    const int tx = threadIdx.x, ty = threadIdx.y;   // 32 x 8
    #pragma unroll
    for (int i = 0; i < 32; i += 8)
        t[ty + i][tx] = W[(size_t)(by * 32 + ty + i) * C + bx * 32 + tx];
    __syncthreads();
    #pragma unroll
    for (int i = 0; i < 32; i += 8) {
        const float v = t[tx][ty + i];
        const __nv_bfloat16 h = __float2bfloat16(v);
        const __nv_bfloat16 l = __float2bfloat16(v - __bfloat162float(h));
        const size_t o = (size_t)(bx * 32 + ty + i) * R + by * 32 + tx;
        Th[o] = h;
        Tl[o] = l;
    }
}

// ---------------- bias: t = 2048 * bv @ Wo + bo ----------------------------
__global__ void bias_partial(const float* __restrict__ bv,
                             const float* __restrict__ Wo)
{
    const int j = blockIdx.x * 128 + threadIdx.x;
    const int i0 = blockIdx.y * 16;
    float s = 0.0f;
    #pragma unroll
    for (int i = 0; i < 16; i++)
        s = fmaf(bv[i0 + i], Wo[(size_t)(i0 + i) * 1024 + j], s);
    g_part[blockIdx.y * 1024 + j] = s;
}

__global__ void bias_final(const float* __restrict__ bo)
{
    const int j = blockIdx.x * 128 + threadIdx.x;
    float s = 0.0f;
    #pragma unroll
    for (int p = 0; p < 64; p++) s += g_part[p * 1024 + j];
    g_t[j] = 2048.0f * s + bo[j];
}

// ---------------------------------------------------------------------------
extern "C" void kernel_launch(void* const* d_in, const int* in_sizes, int n_in,
                              void* d_out, int out_size)
{
    const float* x  = (const float*)d_in[0];
    // d_in[1..5] = encoder_x, Wq, bq, Wk, bk -- mathematically dead
    const float* Wv = (const float*)d_in[6];
    const float* bv = (const float*)d_in[7];
    const float* Wo = (const float*)d_in[8];
    const float* bo = (const float*)d_in[9];
    float* out = (float*)d_out;

    const int D = 1024, M = 8192;

    __nv_bfloat16 *xh, *xl, *Wvh, *Wvl, *WoTh, *WoTl, *WcTh, *WcTl;
    float *Wc, *t;
    cudaGetSymbolAddress((void**)&xh,   g_xh);
    cudaGetSymbolAddress((void**)&xl,   g_xl);
    cudaGetSymbolAddress((void**)&Wvh,  g_Wvh);
    cudaGetSymbolAddress((void**)&Wvl,  g_Wvl);
    cudaGetSymbolAddress((void**)&WoTh, g_WoTh);
    cudaGetSymbolAddress((void**)&WoTl, g_WoTl);
    cudaGetSymbolAddress((void**)&WcTh, g_WcTh);
    cudaGetSymbolAddress((void**)&WcTl, g_WcTl);
    cudaGetSymbolAddress((void**)&Wc,   g_Wc);
    cudaGetSymbolAddress((void**)&t,    g_t);

    static int smem_set = 0;
    if (!smem_set) {
        cudaFuncSetAttribute(gemm_hmma,
                             cudaFuncAttributeMaxDynamicSharedMemorySize,
                             SMEM_BYTES);
        smem_set = 1;
    }

    // conversions
    split_rm<<<(M * D / 4) / 256, 256>>>(x, xh, xl, M * D / 4);
    split_rm<<<(D * D / 4) / 256, 256>>>(Wv, Wvh, Wvl, D * D / 4);
    {
        dim3 g(D / 32, D / 32), b(32, 8);
        split_tr<<<g, b>>>(Wo, WoTh, WoTl, D, D);
    }

    // bias t = 2048*bv@Wo + bo
    {
        dim3 g(8, 64);
        bias_partial<<<g, 128>>>(bv, Wo);
        bias_final<<<8, 128>>>(bo);
    }

    // Wc = Wv @ Wo  (1024^3)
    {
        dim3 g(D / 256, D / 128);
        gemm_hmma<<<g, GT, SMEM_BYTES>>>(Wvh, Wvl, WoTh, WoTl, Wc, nullptr,
                                         D, D, D, 1.0f);
    }
    {
        dim3 g(D / 32, D / 32), b(32, 8);
        split_tr<<<g, b>>>(Wc, WcTh, WcTl, D, D);
    }

    // out = 2048 * x @ Wc + t  (8192 x 1024 x 1024)
    {
        dim3 g(D / 256, M / 128);
        gemm_hmma<<<g, GT, SMEM_BYTES>>>(xh, xl, WcTh, WcTl, out, t,
                                         M, D, D, 2048.0f);
    }
}

// round 5
// speedup vs baseline: 6.5587x; 2.3082x over previous
#include <cuda_runtime.h>
#include <cuda_fp16.h>
#include <stdint.h>

// ============================================================================
// CrossAttention collapses algebraically:
//   softmax over k sums to 1 per query -> sum over (q,k) of scores = L = 2048.
//   einsum 'bvhd,bhqk->bvhd' has no shared contraction index, so attn = v*2048:
//     out = 2048 * x @ (Wv@Wo) + (2048 * bv@Wo + bo)
// encoder_x / Wq / bq / Wk / bk are dead inputs.
//
// R5: legacy mma.sync HMMA is issue-rate-bound (~14 cyc/MMA on sm_103), so
// minimize MMA count: single-pass fp16 (11 mantissa bits -> ~3.8e-4 L2 err)
// instead of 3-pass split-bf16. 3x fewer MMAs.
// gemm1 emits WcT directly in fp16 (WcT = WoT @ Wv^T), killing the transpose.
// ============================================================================

// ---------------- scratch ----------------------------------------------------
__device__ __half g_xh  [8192u * 1024u];
__device__ __half g_Wvh [1024u * 1024u];
__device__ __half g_WoTh[1024u * 1024u];
__device__ __half g_WcTh[1024u * 1024u];
__device__ float  g_part[64 * 1024];
__device__ float  g_t[1024];

// ---------------- helpers ----------------------------------------------------
__device__ __forceinline__ uint32_t smem_u32(const void* p) {
    uint32_t a;
    asm("{ .reg .u64 t; cvta.to.shared.u64 t, %1; cvt.u32.u64 %0, t; }"
        : "=r"(a) : "l"(p));
    return a;
}
__device__ __forceinline__ void cp_async16(uint32_t saddr, const void* gaddr) {
    asm volatile("cp.async.cg.shared.global [%0], [%1], 16;"
                 :: "r"(saddr), "l"(gaddr));
}
#define CP_COMMIT() asm volatile("cp.async.commit_group;" ::: "memory")
#define CP_WAIT0()  asm volatile("cp.async.wait_group 0;" ::: "memory")

// m16n8k16 fp16 MMA, fp32 accumulate
__device__ __forceinline__ void mma16816(float* c, const uint32_t* a,
                                         const uint32_t* b) {
    asm volatile(
        "mma.sync.aligned.m16n8k16.row.col.f32.f16.f16.f32 "
        "{%0,%1,%2,%3}, {%4,%5,%6,%7}, {%8,%9}, {%0,%1,%2,%3};"
        : "+f"(c[0]), "+f"(c[1]), "+f"(c[2]), "+f"(c[3])
        : "r"(a[0]), "r"(a[1]), "r"(a[2]), "r"(a[3]), "r"(b[0]), "r"(b[1]));
}
__device__ __forceinline__ void ldsm4(uint32_t* r, uint32_t addr) {
    asm volatile("ldmatrix.sync.aligned.m8n8.x4.shared.b16 {%0,%1,%2,%3}, [%4];"
                 : "=r"(r[0]), "=r"(r[1]), "=r"(r[2]), "=r"(r[3]) : "r"(addr));
}
// swizzled offset inside a 128B-row tile
__device__ __forceinline__ uint32_t swz(int row, int col) {
    return (uint32_t)(row * 128 + (col ^ ((row & 7) << 4)));
}

// ---------------- single-pass fp16 HMMA GEMM --------------------------------
// C[M,N] = alpha*(A@B^T) + bias[n].  A: [M,K] K-major fp16. B: [N,K] K-major.
// M%128==0, N%BN==0, K%64==0.  8 warps; warp tile 64 x (BN/4).
#define GT 256

template <int BN, typename OutT>
__global__ __launch_bounds__(GT, 1)
void gemm_h(const __half* __restrict__ A, const __half* __restrict__ B,
            OutT* __restrict__ C, const float* __restrict__ bias,
            int M, int N, int K, float alpha)
{
    constexpr uint32_t TA_B = 16384u;          // 128 x 128B
    constexpr uint32_t TB_B = (uint32_t)BN * 128u;
    constexpr uint32_t STG_B = TA_B + TB_B;
    constexpr int NT2 = BN / 64;               // B ldsm groups per warp
    constexpr int WN = BN / 4;                 // warp n-width

    extern __shared__ char smem[];
    const uint32_t sb = smem_u32(smem);
    const int tid = threadIdx.x;
    const int wid = tid >> 5, lane = tid & 31;
    const int g = lane >> 2, tig = lane & 3;
    const int bm = blockIdx.y, bn = blockIdx.x;
    const int wm = (wid & 1) * 64;             // 2 warps over M
    const int wn = (wid >> 1) * WN;            // 4 warps over N
    const int lm = lane >> 3, lr = lane & 7;   // ldmatrix decomposition

    const __half* Ab = A + (size_t)bm * 128 * K;
    const __half* Bb = B + (size_t)bn * BN * K;

    float acc[4][2 * NT2][4];
    #pragma unroll
    for (int mt = 0; mt < 4; mt++)
        #pragma unroll
        for (int nt = 0; nt < 2 * NT2; nt++)
            #pragma unroll
            for (int i = 0; i < 4; i++) acc[mt][nt][i] = 0.0f;

    const int nch = K / 64;

    auto issue = [&](int c) {
        const int k0 = c * 64;
        const uint32_t stg = sb + (uint32_t)(c & 1) * STG_B;
        #pragma unroll
        for (int i = 0; i < 4; i++) {          // A: 128 rows x 128B
            const int li = i * GT + tid;
            const int row = li >> 3, kc = li & 7;
            cp_async16(stg + swz(row, kc * 16),
                       Ab + (size_t)row * K + k0 + kc * 8);
        }
        #pragma unroll
        for (int i = 0; i < BN / 32; i++) {    // B: BN rows x 128B
            const int li = i * GT + tid;
            const int row = li >> 3, kc = li & 7;
            cp_async16(stg + TA_B + swz(row, kc * 16),
                       Bb + (size_t)row * K + k0 + kc * 8);
        }
        CP_COMMIT();
    };

    issue(0);

    for (int c = 0; c < nch; c++) {
        CP_WAIT0();
        __syncthreads();
        if (c + 1 < nch) issue(c + 1);

        const uint32_t tA = sb + (uint32_t)(c & 1) * STG_B;
        const uint32_t tB = tA + TA_B;

        #pragma unroll
        for (int ks = 0; ks < 4; ks++) {
            const int kb = ks * 32;
            uint32_t aF[4][4], bF[NT2][4];
            #pragma unroll
            for (int mt = 0; mt < 4; mt++) {
                const int row = wm + mt * 16 + (lm & 1) * 8 + lr;
                ldsm4(aF[mt], tA + swz(row, kb + (lm >> 1) * 16));
            }
            #pragma unroll
            for (int nt2 = 0; nt2 < NT2; nt2++) {
                const int row = wn + (2 * nt2 + (lm >> 1)) * 8 + lr;
                ldsm4(bF[nt2], tB + swz(row, kb + (lm & 1) * 16));
            }
            #pragma unroll
            for (int mt = 0; mt < 4; mt++)
                #pragma unroll
                for (int nt2 = 0; nt2 < NT2; nt2++) {
                    mma16816(acc[mt][2 * nt2],     aF[mt], &bF[nt2][0]);
                    mma16816(acc[mt][2 * nt2 + 1], aF[mt], &bF[nt2][2]);
                }
        }
        __syncthreads();
    }

    // ---- epilogue
    #pragma unroll
    for (int mt = 0; mt < 4; mt++) {
        const size_t r0 = (size_t)bm * 128 + wm + mt * 16 + g;
        #pragma unroll
        for (int nt = 0; nt < 2 * NT2; nt++) {
            const int c0 = bn * BN + wn + nt * 8 + tig * 2;
            float bx = 0.f, by = 0.f;
            if (bias) { bx = bias[c0]; by = bias[c0 + 1]; }
            float v00 = alpha * acc[mt][nt][0] + bx;
            float v01 = alpha * acc[mt][nt][1] + by;
            float v10 = alpha * acc[mt][nt][2] + bx;
            float v11 = alpha * acc[mt][nt][3] + by;
            if constexpr (sizeof(OutT) == 4) {
                *(float2*)((float*)C + r0 * N + c0)       = make_float2(v00, v01);
                *(float2*)((float*)C + (r0 + 8) * N + c0) = make_float2(v10, v11);
            } else {
                *(__half2*)((__half*)C + r0 * N + c0) =
                    __floats2half2_rn(v00, v01);
                *(__half2*)((__half*)C + (r0 + 8) * N + c0) =
                    __floats2half2_rn(v10, v11);
            }
        }
    }
}

// ---------------- fp32 -> fp16, row-major -----------------------------------
__global__ void cvt_rm(const float* __restrict__ src,
                       __half* __restrict__ dst, int n4)
{
    const int i = blockIdx.x * blockDim.x + threadIdx.x;
    if (i < n4) {
        const float4 v = ((const float4*)src)[i];
        ((__half2*)dst)[2 * i]     = __floats2half2_rn(v.x, v.y);
        ((__half2*)dst)[2 * i + 1] = __floats2half2_rn(v.z, v.w);
    }
}

// ---------------- fp32 [R,C] -> fp16 transposed [C,R] -----------------------
__global__ void cvt_tr(const float* __restrict__ W,
                       __half* __restrict__ T, int R, int C)
{
    __shared__ float t[32][33];
    const int bx = blockIdx.x, by = blockIdx.y;
    const int tx = threadIdx.x, ty = threadIdx.y;   // 32 x 8
    #pragma unroll
    for (int i = 0; i < 32; i += 8)
        t[ty + i][tx] = W[(size_t)(by * 32 + ty + i) * C + bx * 32 + tx];
    __syncthreads();
    #pragma unroll
    for (int i = 0; i < 32; i += 8)
        T[(size_t)(bx * 32 + ty + i) * R + by * 32 + tx] =
            __float2half_rn(t[tx][ty + i]);
}

// ---------------- bias: t = 2048 * bv @ Wo + bo -----------------------------
__global__ void bias_partial(const float* __restrict__ bv,
                             const float* __restrict__ Wo)
{
    const int j = blockIdx.x * 128 + threadIdx.x;
    const int i0 = blockIdx.y * 16;
    float s = 0.0f;
    #pragma unroll
    for (int i = 0; i < 16; i++)
        s = fmaf(bv[i0 + i], Wo[(size_t)(i0 + i) * 1024 + j], s);
    g_part[blockIdx.y * 1024 + j] = s;
}

__global__ void bias_final(const float* __restrict__ bo)
{
    const int j = blockIdx.x * 128 + threadIdx.x;
    float s = 0.0f;
    #pragma unroll
    for (int p = 0; p < 64; p++) s += g_part[p * 1024 + j];
    g_t[j] = 2048.0f * s + bo[j];
}

// ---------------------------------------------------------------------------
extern "C" void kernel_launch(void* const* d_in, const int* in_sizes, int n_in,
                              void* d_out, int out_size)
{
    const float* x  = (const float*)d_in[0];
    // d_in[1..5] = encoder_x, Wq, bq, Wk, bk -- mathematically dead
    const float* Wv = (const float*)d_in[6];
    const float* bv = (const float*)d_in[7];
    const float* Wo = (const float*)d_in[8];
    const float* bo = (const float*)d_in[9];
    float* out = (float*)d_out;

    const int D = 1024, M = 8192;

    __half *xh, *Wvh, *WoTh, *WcTh;
    float *t;
    cudaGetSymbolAddress((void**)&xh,   g_xh);
    cudaGetSymbolAddress((void**)&Wvh,  g_Wvh);
    cudaGetSymbolAddress((void**)&WoTh, g_WoTh);
    cudaGetSymbolAddress((void**)&WcTh, g_WcTh);
    cudaGetSymbolAddress((void**)&t,    g_t);

    constexpr uint32_t SM1 = 2u * (16384u + 128u * 128u);  //  64KB (BN=128)
    constexpr uint32_t SM2 = 2u * (16384u + 256u * 128u);  //  96KB (BN=256)

    static int smem_set = 0;
    if (!smem_set) {
        cudaFuncSetAttribute(gemm_h<128, __half>,
                             cudaFuncAttributeMaxDynamicSharedMemorySize, SM1);
        cudaFuncSetAttribute(gemm_h<256, float>,
                             cudaFuncAttributeMaxDynamicSharedMemorySize, SM2);
        smem_set = 1;
    }

    // conversions
    cvt_rm<<<(M * D / 4) / 256, 256>>>(x, xh, M * D / 4);
    cvt_rm<<<(D * D / 4) / 256, 256>>>(Wv, Wvh, D * D / 4);
    {
        dim3 g(D / 32, D / 32), b(32, 8);
        cvt_tr<<<g, b>>>(Wo, WoTh, D, D);
    }

    // bias t = 2048*bv@Wo + bo
    {
        dim3 g(8, 64);
        bias_partial<<<g, 128>>>(bv, Wo);
        bias_final<<<8, 128>>>(bo);
    }

    // gemm1: WcT = WoT @ Wv^T  (fp16 out, [N,K] layout for gemm2's B operand)
    //   C[m,n] = sum_k WoT[m,k] * Wv[n,k] = Wc[n,m]  ✓
    {
        dim3 g(D / 128, D / 128);
        gemm_h<128, __half><<<g, GT, SM1>>>(WoTh, Wvh, WcTh, nullptr,
                                            D, D, D, 1.0f);
    }

    // gemm2: out = 2048 * x @ Wc + t   (A=xh, B=WcT [N,K])
    {
        dim3 g(D / 256, M / 128);
        gemm_h<256, float><<<g, GT, SM2>>>(xh, WcTh, out, t,
                                           M, D, D, 2048.0f);
    }
}

// round 6
// speedup vs baseline: 6.8542x; 1.0451x over previous
#include <cuda_runtime.h>
#include <cuda_fp16.h>
#include <stdint.h>

// ============================================================================
// CrossAttention collapses algebraically:
//   softmax over k sums to 1 per query -> sum over (q,k) of scores = L = 2048.
//   einsum 'bvhd,bhqk->bvhd' has no shared contraction index, so attn = v*2048:
//     out = 2048 * x @ (Wv@Wo) + (2048 * bv@Wo + bo)
// encoder_x / Wq / bq / Wk / bk are dead inputs.
//
// Legacy mma.sync HMMA runs at ~14.8 cyc/SMSP per m16n8k16 on sm_103 (dtype-
// independent) -> time ~ MMA count. Single-pass fp16 (~4e-4 L2 err).
// R6: gemm2 consumes x in fp32 directly (no cvt pass); gemm1 on 128 CTAs;
// wider bias grid.
// ============================================================================

// ---------------- scratch ----------------------------------------------------
__device__ __half g_Wvh [1024u * 1024u];
__device__ __half g_WoTh[1024u * 1024u];
__device__ __half g_WcTh[1024u * 1024u];
__device__ float  g_part[128 * 1024];
__device__ float  g_t[1024];

// ---------------- helpers ----------------------------------------------------
__device__ __forceinline__ uint32_t smem_u32(const void* p) {
    uint32_t a;
    asm("{ .reg .u64 t; cvta.to.shared.u64 t, %1; cvt.u32.u64 %0, t; }"
        : "=r"(a) : "l"(p));
    return a;
}
__device__ __forceinline__ void cp_async16(uint32_t saddr, const void* gaddr) {
    asm volatile("cp.async.cg.shared.global [%0], [%1], 16;"
                 :: "r"(saddr), "l"(gaddr));
}
#define CP_COMMIT() asm volatile("cp.async.commit_group;" ::: "memory")
#define CP_WAIT0()  asm volatile("cp.async.wait_group 0;" ::: "memory")

__device__ __forceinline__ void mma16816(float* c, const uint32_t* a,
                                         const uint32_t* b) {
    asm volatile(
        "mma.sync.aligned.m16n8k16.row.col.f32.f16.f16.f32 "
        "{%0,%1,%2,%3}, {%4,%5,%6,%7}, {%8,%9}, {%0,%1,%2,%3};"
        : "+f"(c[0]), "+f"(c[1]), "+f"(c[2]), "+f"(c[3])
        : "r"(a[0]), "r"(a[1]), "r"(a[2]), "r"(a[3]), "r"(b[0]), "r"(b[1]));
}
__device__ __forceinline__ void ldsm4(uint32_t* r, uint32_t addr) {
    asm volatile("ldmatrix.sync.aligned.m8n8.x4.shared.b16 {%0,%1,%2,%3}, [%4];"
                 : "=r"(r[0]), "=r"(r[1]), "=r"(r[2]), "=r"(r[3]) : "r"(addr));
}
// fp16 tile (128B rows): 16B-granule XOR swizzle
__device__ __forceinline__ uint32_t swzH(int row, int col) {
    return (uint32_t)(row * 128 + (col ^ ((row & 7) << 4)));
}
// fp32 tile (256B rows): 32B-granule XOR swizzle
__device__ __forceinline__ uint32_t swzF(int row, int col) {
    return (uint32_t)(row * 256 + (col ^ ((row & 7) << 5)));
}
__device__ __forceinline__ uint32_t h2u(__half2 h) {
    union { __half2 h; uint32_t u; } c; c.h = h; return c.u;
}

// ---------------- fp16 HMMA GEMM (A fp16 or fp32) ---------------------------
// C[M,N] = alpha*(A@B^T) + bias[n].  A: [M,K] K-major (fp16 or fp32).
// B: [N,K] K-major fp16.  M%128==0, N%BN==0, K%64==0. 8 warps, warp 64x(BN/4).
#define GT 256

template <int BN, bool AF32, typename AT, typename OutT>
__global__ __launch_bounds__(GT, 1)
void gemm_h(const AT* __restrict__ A, const __half* __restrict__ B,
            OutT* __restrict__ C, const float* __restrict__ bias,
            int M, int N, int K, float alpha)
{
    constexpr uint32_t ARB  = AF32 ? 256u : 128u;     // A smem row bytes
    constexpr uint32_t TA_B = 128u * ARB;
    constexpr uint32_t TB_B = (uint32_t)BN * 128u;
    constexpr uint32_t STG_B = TA_B + TB_B;
    constexpr int NT2 = BN / 64;
    constexpr int WN = BN / 4;

    extern __shared__ char smem[];
    const uint32_t sb = smem_u32(smem);
    const int tid = threadIdx.x;
    const int wid = tid >> 5, lane = tid & 31;
    const int g = lane >> 2, tig = lane & 3;
    const int bm = blockIdx.y, bn = blockIdx.x;
    const int wm = (wid & 1) * 64;
    const int wn = (wid >> 1) * WN;
    const int lm = lane >> 3, lr = lane & 7;

    const AT* Ab = A + (size_t)bm * 128 * K;
    const __half* Bb = B + (size_t)bn * BN * K;

    float acc[4][2 * NT2][4];
    #pragma unroll
    for (int mt = 0; mt < 4; mt++)
        #pragma unroll
        for (int nt = 0; nt < 2 * NT2; nt++)
            #pragma unroll
            for (int i = 0; i < 4; i++) acc[mt][nt][i] = 0.0f;

    const int nch = K / 64;

    auto issue = [&](int c) {
        const int k0 = c * 64;
        const uint32_t stg = sb + (uint32_t)(c & 1) * STG_B;
        // A tile: 128 rows, 64 k-elements (= ARB bytes per row)
        constexpr int AG = (int)(128u * ARB / 16u) / GT;  // granules per thread
        #pragma unroll
        for (int i = 0; i < AG; i++) {
            const int li = i * GT + tid;
            const int gpr = (int)(ARB / 16u);             // granules per row
            const int row = li / gpr, gc = li % gpr;
            if constexpr (AF32)
                cp_async16(stg + swzF(row, gc * 16),
                           (const float*)Ab + (size_t)row * K + k0 + gc * 4);
            else
                cp_async16(stg + swzH(row, gc * 16),
                           (const __half*)Ab + (size_t)row * K + k0 + gc * 8);
        }
        // B tile: BN rows x 128B
        #pragma unroll
        for (int i = 0; i < BN / 32; i++) {
            const int li = i * GT + tid;
            const int row = li >> 3, kc = li & 7;
            cp_async16(stg + TA_B + swzH(row, kc * 16),
                       Bb + (size_t)row * K + k0 + kc * 8);
        }
        CP_COMMIT();
    };

    issue(0);

    for (int c = 0; c < nch; c++) {
        CP_WAIT0();
        __syncthreads();
        if (c + 1 < nch) issue(c + 1);

        const uint32_t tA = sb + (uint32_t)(c & 1) * STG_B;
        const uint32_t tB = tA + TA_B;

        #pragma unroll
        for (int ks = 0; ks < 4; ks++) {
            const int kb = ks * 32;                 // byte offset in fp16 tile
            uint32_t aF[4][4], bF[NT2][4];

            if constexpr (AF32) {
                // element col (fp32): ce = ks*16 + 2*tig; regs:
                // a0:(g,ce) a1:(g+8,ce) a2:(g,ce+8) a3:(g+8,ce+8)
                const int cb = (ks * 16 + 2 * tig) * 4;   // byte col
                #pragma unroll
                for (int mt = 0; mt < 4; mt++) {
                    const int r0 = wm + mt * 16 + g, r1 = r0 + 8;
                    float2 v00 = *(const float2*)(smem + swzF(r0, cb));
                    float2 v10 = *(const float2*)(smem + swzF(r1, cb) );
                    float2 v01 = *(const float2*)(smem + swzF(r0, cb + 32));
                    float2 v11 = *(const float2*)(smem + swzF(r1, cb + 32));
                    // adjust: swzF returns offset from tile base; add (tA - sb)
                    (void)v00; (void)v10; (void)v01; (void)v11;
                    // recompute with proper base:
                    const char* base = (const char*)smem + (tA - sb);
                    v00 = *(const float2*)(base + swzF(r0, cb));
                    v10 = *(const float2*)(base + swzF(r1, cb));
                    v01 = *(const float2*)(base + swzF(r0, cb + 32));
                    v11 = *(const float2*)(base + swzF(r1, cb + 32));
                    aF[mt][0] = h2u(__floats2half2_rn(v00.x, v00.y));
                    aF[mt][1] = h2u(__floats2half2_rn(v10.x, v10.y));
                    aF[mt][2] = h2u(__floats2half2_rn(v01.x, v01.y));
                    aF[mt][3] = h2u(__floats2half2_rn(v11.x, v11.y));
                }
            } else {
                #pragma unroll
                for (int mt = 0; mt < 4; mt++) {
                    const int row = wm + mt * 16 + (lm & 1) * 8 + lr;
                    ldsm4(aF[mt], tA + swzH(row, kb + (lm >> 1) * 16));
                }
            }
            #pragma unroll
            for (int nt2 = 0; nt2 < NT2; nt2++) {
                const int row = wn + (2 * nt2 + (lm >> 1)) * 8 + lr;
                ldsm4(bF[nt2], tB + swzH(row, kb + (lm & 1) * 16));
            }
            #pragma unroll
            for (int mt = 0; mt < 4; mt++)
                #pragma unroll
                for (int nt2 = 0; nt2 < NT2; nt2++) {
                    mma16816(acc[mt][2 * nt2],     aF[mt], &bF[nt2][0]);
                    mma16816(acc[mt][2 * nt2 + 1], aF[mt], &bF[nt2][2]);
                }
        }
        __syncthreads();
    }

    // ---- epilogue
    #pragma unroll
    for (int mt = 0; mt < 4; mt++) {
        const size_t r0 = (size_t)bm * 128 + wm + mt * 16 + g;
        #pragma unroll
        for (int nt = 0; nt < 2 * NT2; nt++) {
            const int c0 = bn * BN + wn + nt * 8 + tig * 2;
            float bx = 0.f, by = 0.f;
            if (bias) { bx = bias[c0]; by = bias[c0 + 1]; }
            float v00 = alpha * acc[mt][nt][0] + bx;
            float v01 = alpha * acc[mt][nt][1] + by;
            float v10 = alpha * acc[mt][nt][2] + bx;
            float v11 = alpha * acc[mt][nt][3] + by;
            if constexpr (sizeof(OutT) == 4) {
                *(float2*)((float*)C + r0 * N + c0)       = make_float2(v00, v01);
                *(float2*)((float*)C + (r0 + 8) * N + c0) = make_float2(v10, v11);
            } else {
                *(__half2*)((__half*)C + r0 * N + c0) =
                    __floats2half2_rn(v00, v01);
                *(__half2*)((__half*)C + (r0 + 8) * N + c0) =
                    __floats2half2_rn(v10, v11);
            }
        }
    }
}

// ---------------- fp32 -> fp16, row-major -----------------------------------
__global__ void cvt_rm(const float* __restrict__ src,
                       __half* __restrict__ dst, int n4)
{
    const int i = blockIdx.x * blockDim.x + threadIdx.x;
    if (i < n4) {
        const float4 v = ((const float4*)src)[i];
        ((__half2*)dst)[2 * i]     = __floats2half2_rn(v.x, v.y);
        ((__half2*)dst)[2 * i + 1] = __floats2half2_rn(v.z, v.w);
    }
}

// ---------------- fp32 [R,C] -> fp16 transposed [C,R] -----------------------
__global__ void cvt_tr(const float* __restrict__ W,
                       __half* __restrict__ T, int R, int C)
{
    __shared__ float t[32][33];
    const int bx = blockIdx.x, by = blockIdx.y;
    const int tx = threadIdx.x, ty = threadIdx.y;   // 32 x 8
    #pragma unroll
    for (int i = 0; i < 32; i += 8)
        t[ty + i][tx] = W[(size_t)(by * 32 + ty + i) * C + bx * 32 + tx];
    __syncthreads();
    #pragma unroll
    for (int i = 0; i < 32; i += 8)
        T[(size_t)(bx * 32 + ty + i) * R + by * 32 + tx] =
            __float2half_rn(t[tx][ty + i]);
}

// ---------------- bias: t = 2048 * bv @ Wo + bo -----------------------------
__global__ void bias_partial(const float* __restrict__ bv,
                             const float* __restrict__ Wo)
{
    const int j = blockIdx.x * 128 + threadIdx.x;
    const int i0 = blockIdx.y * 8;
    float s = 0.0f;
    #pragma unroll
    for (int i = 0; i < 8; i++)
        s = fmaf(bv[i0 + i], Wo[(size_t)(i0 + i) * 1024 + j], s);
    g_part[blockIdx.y * 1024 + j] = s;
}

__global__ void bias_final(const float* __restrict__ bo)
{
    const int j = blockIdx.x * 128 + threadIdx.x;
    float s = 0.0f;
    #pragma unroll
    for (int p = 0; p < 128; p++) s += g_part[p * 1024 + j];
    g_t[j] = 2048.0f * s + bo[j];
}

// ---------------------------------------------------------------------------
extern "C" void kernel_launch(void* const* d_in, const int* in_sizes, int n_in,
                              void* d_out, int out_size)
{
    const float* x  = (const float*)d_in[0];
    // d_in[1..5] = encoder_x, Wq, bq, Wk, bk -- mathematically dead
    const float* Wv = (const float*)d_in[6];
    const float* bv = (const float*)d_in[7];
    const float* Wo = (const float*)d_in[8];
    const float* bo = (const float*)d_in[9];
    float* out = (float*)d_out;

    const int D = 1024, M = 8192;

    __half *Wvh, *WoTh, *WcTh;
    float *t;
    cudaGetSymbolAddress((void**)&Wvh,  g_Wvh);
    cudaGetSymbolAddress((void**)&WoTh, g_WoTh);
    cudaGetSymbolAddress((void**)&WcTh, g_WcTh);
    cudaGetSymbolAddress((void**)&t,    g_t);

    constexpr uint32_t SM1 = 2u * (128u * 128u + 64u * 128u);   //  48KB
    constexpr uint32_t SM2 = 2u * (128u * 256u + 256u * 128u);  // 128KB

    static int smem_set = 0;
    if (!smem_set) {
        cudaFuncSetAttribute((const void*)gemm_h<64, false, __half, __half>,
                             cudaFuncAttributeMaxDynamicSharedMemorySize, SM1);
        cudaFuncSetAttribute((const void*)gemm_h<256, true, float, float>,
                             cudaFuncAttributeMaxDynamicSharedMemorySize, SM2);
        smem_set = 1;
    }

    // weight conversions
    cvt_rm<<<(D * D / 4) / 256, 256>>>(Wv, Wvh, D * D / 4);
    {
        dim3 g(D / 32, D / 32), b(32, 8);
        cvt_tr<<<g, b>>>(Wo, WoTh, D, D);
    }

    // bias t = 2048*bv@Wo + bo
    {
        dim3 g(8, 128);
        bias_partial<<<g, 128>>>(bv, Wo);
        bias_final<<<8, 128>>>(bo);
    }

    // gemm1: WcT = WoT @ Wv^T  (128 CTAs; fp16 out in [N,K] layout for gemm2)
    {
        dim3 g(D / 64, D / 128);
        gemm_h<64, false, __half, __half><<<g, GT, SM1>>>(
            WoTh, Wvh, WcTh, nullptr, D, D, D, 1.0f);
    }

    // gemm2: out = 2048 * x @ Wc + t   (A = x in fp32, converted in-kernel)
    {
        dim3 g(D / 256, M / 128);
        gemm_h<256, true, float, float><<<g, GT, SM2>>>(
            x, WcTh, out, t, M, D, D, 2048.0f);
    }
}

// round 7
// speedup vs baseline: 7.8962x; 1.1520x over previous
#include <cuda_runtime.h>
#include <cuda_fp16.h>
#include <stdint.h>

// ============================================================================
// CrossAttention collapses algebraically:
//   softmax over k sums to 1 per query -> sum over (q,k) of scores = L = 2048.
//   einsum 'bvhd,bhqk->bvhd' has no shared contraction index, so attn = v*2048:
//     out = 2048 * x @ (Wv@Wo) + (2048 * bv@Wo + bo)
// encoder_x / Wq / bq / Wk / bk are dead inputs.
//
// Legacy mma.sync HMMA: ~14.8 cyc/SMSP per m16n8k16 on sm_103 -> time ~ #MMA.
// R7: (a) gemm2 64x128 tiles / 1024 CTAs to kill wave quantization (67->59),
//     (b) bias folded into gemm1 launch as 16 concurrent CTAs (free),
//     (c) single fused weight-prep kernel. 3 launches total.
// ============================================================================

// ---------------- scratch ----------------------------------------------------
__device__ __half g_Wvh [1024u * 1024u];
__device__ __half g_WoTh[1024u * 1024u];
__device__ __half g_WcTh[1024u * 1024u];
__device__ float  g_t[1024];

// ---------------- helpers ----------------------------------------------------
__device__ __forceinline__ uint32_t smem_u32(const void* p) {
    uint32_t a;
    asm("{ .reg .u64 t; cvta.to.shared.u64 t, %1; cvt.u32.u64 %0, t; }"
        : "=r"(a) : "l"(p));
    return a;
}
__device__ __forceinline__ void cp_async16(uint32_t saddr, const void* gaddr) {
    asm volatile("cp.async.cg.shared.global [%0], [%1], 16;"
                 :: "r"(saddr), "l"(gaddr));
}
#define CP_COMMIT() asm volatile("cp.async.commit_group;" ::: "memory")
#define CP_WAIT0()  asm volatile("cp.async.wait_group 0;" ::: "memory")

__device__ __forceinline__ void mma16816(float* c, const uint32_t* a,
                                         const uint32_t* b) {
    asm volatile(
        "mma.sync.aligned.m16n8k16.row.col.f32.f16.f16.f32 "
        "{%0,%1,%2,%3}, {%4,%5,%6,%7}, {%8,%9}, {%0,%1,%2,%3};"
        : "+f"(c[0]), "+f"(c[1]), "+f"(c[2]), "+f"(c[3])
        : "r"(a[0]), "r"(a[1]), "r"(a[2]), "r"(a[3]), "r"(b[0]), "r"(b[1]));
}
__device__ __forceinline__ void ldsm4(uint32_t* r, uint32_t addr) {
    asm volatile("ldmatrix.sync.aligned.m8n8.x4.shared.b16 {%0,%1,%2,%3}, [%4];"
                 : "=r"(r[0]), "=r"(r[1]), "=r"(r[2]), "=r"(r[3]) : "r"(addr));
}
// fp16 tile (128B rows): 16B-granule XOR swizzle
__device__ __forceinline__ uint32_t swzH(int row, int col) {
    return (uint32_t)(row * 128 + (col ^ ((row & 7) << 4)));
}
// fp32 tile (256B rows): 32B-granule XOR swizzle
__device__ __forceinline__ uint32_t swzF(int row, int col) {
    return (uint32_t)(row * 256 + (col ^ ((row & 7) << 5)));
}
__device__ __forceinline__ uint32_t h2u(__half2 h) {
    union { __half2 h; uint32_t u; } c; c.h = h; return c.u;
}

// ---------------- generalized fp16 HMMA GEMM --------------------------------
// C[M,N] = alpha*(A@B^T) + bias[n].  A: [M,K] K-major (fp16 or fp32).
// B: [N,K] K-major fp16.  WMxWN warp grid over a BMxBN tile.
// If BIASROW: blocks with blockIdx.y == gridDim.y-1 instead compute
//   tvec[j] = 2048 * sum_i bv[i]*Wo32[i*N+j] + bo[j]   (64 cols per CTA).
template <int BM, int BN, int WM, int WN, bool AF32, bool BIASROW,
          typename AT, typename OutT>
__global__ __launch_bounds__(WM * WN * 32)
void gemm_h(const AT* __restrict__ A, const __half* __restrict__ B,
            OutT* __restrict__ C, const float* __restrict__ bias,
            const float* __restrict__ bv, const float* __restrict__ Wo32,
            const float* __restrict__ bo, float* __restrict__ tvec,
            int M, int N, int K, float alpha)
{
    constexpr int NTHR = WM * WN * 32;
    constexpr uint32_t ARB  = AF32 ? 256u : 128u;     // A smem row bytes
    constexpr uint32_t TA_B = (uint32_t)BM * ARB;
    constexpr uint32_t TB_B = (uint32_t)BN * 128u;
    constexpr uint32_t STG_B = TA_B + TB_B;
    constexpr int MT  = BM / WM / 16;                 // 16-row m-tiles per warp
    constexpr int NT2 = BN / WN / 16;                 // 16-col n-groups per warp

    const int tid = threadIdx.x;

    if constexpr (BIASROW) {
        if (blockIdx.y == gridDim.y - 1) {
            __shared__ float red[4][64];
            const int c = tid & 63, q = tid >> 6;
            const int j = blockIdx.x * 64 + c;
            const int i0 = q * 256;
            float s = 0.0f;
            #pragma unroll 8
            for (int i = 0; i < 256; i++)
                s = fmaf(bv[i0 + i], Wo32[(size_t)(i0 + i) * N + j], s);
            red[q][c] = s;
            __syncthreads();
            if (q == 0)
                tvec[j] = 2048.0f * (red[0][c] + red[1][c] +
                                     red[2][c] + red[3][c]) + bo[j];
            return;
        }
    }

    extern __shared__ char smem[];
    const uint32_t sb = smem_u32(smem);
    const int wid = tid >> 5, lane = tid & 31;
    const int g = lane >> 2, tig = lane & 3;
    const int bm = blockIdx.y, bn = blockIdx.x;
    const int wm = (wid % WM) * (BM / WM);
    const int wn = (wid / WM) * (BN / WN);
    const int lm = lane >> 3, lr = lane & 7;

    const AT* Ab = A + (size_t)bm * BM * K;
    const __half* Bb = B + (size_t)bn * BN * K;

    float acc[MT][2 * NT2][4];
    #pragma unroll
    for (int mt = 0; mt < MT; mt++)
        #pragma unroll
        for (int nt = 0; nt < 2 * NT2; nt++)
            #pragma unroll
            for (int i = 0; i < 4; i++) acc[mt][nt][i] = 0.0f;

    const int nch = K / 64;

    auto issue = [&](int c) {
        const int k0 = c * 64;
        const uint32_t stg = sb + (uint32_t)(c & 1) * STG_B;
        constexpr int GPR = (int)(ARB / 16u);              // granules per A row
        constexpr int AG = BM * GPR / NTHR;
        #pragma unroll
        for (int i = 0; i < AG; i++) {
            const int li = i * NTHR + tid;
            const int row = li / GPR, gc = li % GPR;
            if constexpr (AF32)
                cp_async16(stg + swzF(row, gc * 16),
                           (const float*)Ab + (size_t)row * K + k0 + gc * 4);
            else
                cp_async16(stg + swzH(row, gc * 16),
                           (const __half*)Ab + (size_t)row * K + k0 + gc * 8);
        }
        constexpr int BG = BN * 8 / NTHR;
        #pragma unroll
        for (int i = 0; i < BG; i++) {
            const int li = i * NTHR + tid;
            const int row = li >> 3, kc = li & 7;
            cp_async16(stg + TA_B + swzH(row, kc * 16),
                       Bb + (size_t)row * K + k0 + kc * 8);
        }
        CP_COMMIT();
    };

    issue(0);

    for (int c = 0; c < nch; c++) {
        CP_WAIT0();
        __syncthreads();
        if (c + 1 < nch) issue(c + 1);

        const char* baseA = smem + (size_t)(c & 1) * STG_B;
        const uint32_t tA = sb + (uint32_t)(c & 1) * STG_B;
        const uint32_t tB = tA + TA_B;

        #pragma unroll
        for (int ks = 0; ks < 4; ks++) {
            const int kb = ks * 32;                 // fp16-tile byte col
            uint32_t aF[MT][4], bF[NT2][4];

            if constexpr (AF32) {
                const int cb = ks * 64 + tig * 8;   // fp32-tile byte col
                #pragma unroll
                for (int mt = 0; mt < MT; mt++) {
                    const int r0 = wm + mt * 16 + g, r1 = r0 + 8;
                    float2 v00 = *(const float2*)(baseA + swzF(r0, cb));
                    float2 v10 = *(const float2*)(baseA + swzF(r1, cb));
                    float2 v01 = *(const float2*)(baseA + swzF(r0, cb + 32));
                    float2 v11 = *(const float2*)(baseA + swzF(r1, cb + 32));
                    aF[mt][0] = h2u(__floats2half2_rn(v00.x, v00.y));
                    aF[mt][1] = h2u(__floats2half2_rn(v10.x, v10.y));
                    aF[mt][2] = h2u(__floats2half2_rn(v01.x, v01.y));
                    aF[mt][3] = h2u(__floats2half2_rn(v11.x, v11.y));
                }
            } else {
                #pragma unroll
                for (int mt = 0; mt < MT; mt++) {
                    const int row = wm + mt * 16 + (lm & 1) * 8 + lr;
                    ldsm4(aF[mt], tA + swzH(row, kb + (lm >> 1) * 16));
                }
            }
            #pragma unroll
            for (int nt2 = 0; nt2 < NT2; nt2++) {
                const int row = wn + (2 * nt2 + (lm >> 1)) * 8 + lr;
                ldsm4(bF[nt2], tB + swzH(row, kb + (lm & 1) * 16));
            }
            #pragma unroll
            for (int mt = 0; mt < MT; mt++)
                #pragma unroll
                for (int nt2 = 0; nt2 < NT2; nt2++) {
                    mma16816(acc[mt][2 * nt2],     aF[mt], &bF[nt2][0]);
                    mma16816(acc[mt][2 * nt2 + 1], aF[mt], &bF[nt2][2]);
                }
        }
        __syncthreads();
    }

    // ---- epilogue
    #pragma unroll
    for (int mt = 0; mt < MT; mt++) {
        const size_t r0 = (size_t)bm * BM + wm + mt * 16 + g;
        #pragma unroll
        for (int nt = 0; nt < 2 * NT2; nt++) {
            const int c0 = bn * BN + wn + nt * 8 + tig * 2;
            float bx = 0.f, by = 0.f;
            if (bias) { bx = bias[c0]; by = bias[c0 + 1]; }
            float v00 = alpha * acc[mt][nt][0] + bx;
            float v01 = alpha * acc[mt][nt][1] + by;
            float v10 = alpha * acc[mt][nt][2] + bx;
            float v11 = alpha * acc[mt][nt][3] + by;
            if constexpr (sizeof(OutT) == 4) {
                *(float2*)((float*)C + r0 * N + c0)       = make_float2(v00, v01);
                *(float2*)((float*)C + (r0 + 8) * N + c0) = make_float2(v10, v11);
            } else {
                *(__half2*)((__half*)C + r0 * N + c0) =
                    __floats2half2_rn(v00, v01);
                *(__half2*)((__half*)C + (r0 + 8) * N + c0) =
                    __floats2half2_rn(v10, v11);
            }
        }
    }
}

// ---------------- fused weight prep -----------------------------------------
// block (32,8), grid (32,32): transposes a 32x32 tile of Wo into fp16 WoT,
// and converts one 256-float4 slice of Wv to fp16.
__global__ void prep_weights(const float* __restrict__ Wv,
                             const float* __restrict__ Wo,
                             __half* __restrict__ Wvh,
                             __half* __restrict__ WoT)
{
    __shared__ float t[32][33];
    const int bx = blockIdx.x, by = blockIdx.y;
    const int tx = threadIdx.x, ty = threadIdx.y;
    const int R = 1024, C = 1024;

    #pragma unroll
    for (int i = 0; i < 32; i += 8)
        t[ty + i][tx] = Wo[(size_t)(by * 32 + ty + i) * C + bx * 32 + tx];

    // Wv cvt slice (no sync needed; independent data)
    {
        const int bid = by * 32 + bx;                 // 0..1023
        const int idx = bid * 256 + ty * 32 + tx;     // float4 index
        const float4 v = ((const float4*)Wv)[idx];
        ((__half2*)Wvh)[2 * idx]     = __floats2half2_rn(v.x, v.y);
        ((__half2*)Wvh)[2 * idx + 1] = __floats2half2_rn(v.z, v.w);
    }

    __syncthreads();
    #pragma unroll
    for (int i = 0; i < 32; i += 8)
        WoT[(size_t)(bx * 32 + ty + i) * R + by * 32 + tx] =
            __float2half_rn(t[tx][ty + i]);
}

// ---------------------------------------------------------------------------
extern "C" void kernel_launch(void* const* d_in, const int* in_sizes, int n_in,
                              void* d_out, int out_size)
{
    const float* x  = (const float*)d_in[0];
    // d_in[1..5] = encoder_x, Wq, bq, Wk, bk -- mathematically dead
    const float* Wv = (const float*)d_in[6];
    const float* bv = (const float*)d_in[7];
    const float* Wo = (const float*)d_in[8];
    const float* bo = (const float*)d_in[9];
    float* out = (float*)d_out;

    const int D = 1024, M = 8192;

    __half *Wvh, *WoTh, *WcTh;
    float *t;
    cudaGetSymbolAddress((void**)&Wvh,  g_Wvh);
    cudaGetSymbolAddress((void**)&WoTh, g_WoTh);
    cudaGetSymbolAddress((void**)&WcTh, g_WcTh);
    cudaGetSymbolAddress((void**)&t,    g_t);

    // gemm1: BM=128 BN=64, 8 warps, fp16 A  -> stage (16+8)KB, x2 = 48KB
    constexpr uint32_t SM1 = 2u * (128u * 128u + 64u * 128u);
    // gemm2: BM=64 BN=128, 4 warps, fp32 A  -> stage (16+16)KB, x2 = 64KB
    constexpr uint32_t SM2 = 2u * (64u * 256u + 128u * 128u);

    static int smem_set = 0;
    if (!smem_set) {
        cudaFuncSetAttribute(
            (const void*)gemm_h<128, 64, 2, 4, false, true, __half, __half>,
            cudaFuncAttributeMaxDynamicSharedMemorySize, SM1);
        cudaFuncSetAttribute(
            (const void*)gemm_h<64, 128, 2, 2, true, false, float, float>,
            cudaFuncAttributeMaxDynamicSharedMemorySize, SM2);
        smem_set = 1;
    }

    // 1) fused weight conversions
    {
        dim3 g(32, 32), b(32, 8);
        prep_weights<<<g, b>>>(Wv, Wo, Wvh, WoTh);
    }

    // 2) gemm1: WcT = WoT @ Wv^T  (128 CTAs) + 16 bias CTAs computing t
    {
        dim3 g(D / 64, D / 128 + 1);   // (16, 9); by==8 -> bias row
        gemm_h<128, 64, 2, 4, false, true, __half, __half><<<g, 256, SM1>>>(
            WoTh, Wvh, WcTh, nullptr, bv, Wo, bo, t, D, D, D, 1.0f);
    }

    // 3) gemm2: out = 2048 * x @ Wc + t   (fp32 A direct; 1024 CTAs)
    {
        dim3 g(D / 128, M / 64);       // (8, 128)
        gemm_h<64, 128, 2, 2, true, false, float, float><<<g, 128, SM2>>>(
            x, WcTh, out, t, nullptr, nullptr, nullptr, nullptr,
            M, D, D, 2048.0f);
    }
}

// round 8
// speedup vs baseline: 8.1083x; 1.0269x over previous
#include <cuda_runtime.h>
#include <cuda_fp16.h>
#include <stdint.h>

// ============================================================================
// CrossAttention collapses algebraically:
//   softmax over k sums to 1 per query -> sum over (q,k) of scores = L = 2048.
//   einsum 'bvhd,bhqk->bvhd' has no shared contraction index, so attn = v*2048:
//     out = 2048 * x @ (Wv@Wo) + (2048 * bv@Wo + bo)
// encoder_x / Wq / bq / Wk / bk are dead inputs.
//
// Legacy mma.sync HMMA: ~14.8 cyc/SMSP per m16n8k16 on sm_103 -> time ~ #MMA.
// R8: prep kernel eliminated — gemm1 consumes fp32 Wo/Wv directly (in-kernel
// fp16 conversion inside the MMA issue shadow). Two launches total:
//   1) gemm1: WcT = Wo^T @ Wv^T (fp16 out) + 16 bias CTAs computing t
//   2) gemm2: out = 2048 * x @ Wc + t (x consumed fp32 directly)
// ============================================================================

// ---------------- scratch ----------------------------------------------------
__device__ __half g_WcTh[1024u * 1024u];
__device__ float  g_t[1024];

// ---------------- helpers ----------------------------------------------------
__device__ __forceinline__ uint32_t smem_u32(const void* p) {
    uint32_t a;
    asm("{ .reg .u64 t; cvta.to.shared.u64 t, %1; cvt.u32.u64 %0, t; }"
        : "=r"(a) : "l"(p));
    return a;
}
__device__ __forceinline__ void cp_async16(uint32_t saddr, const void* gaddr) {
    asm volatile("cp.async.cg.shared.global [%0], [%1], 16;"
                 :: "r"(saddr), "l"(gaddr));
}
#define CP_COMMIT() asm volatile("cp.async.commit_group;" ::: "memory")
#define CP_WAIT0()  asm volatile("cp.async.wait_group 0;" ::: "memory")

__device__ __forceinline__ void mma16816(float* c, const uint32_t* a,
                                         const uint32_t* b) {
    asm volatile(
        "mma.sync.aligned.m16n8k16.row.col.f32.f16.f16.f32 "
        "{%0,%1,%2,%3}, {%4,%5,%6,%7}, {%8,%9}, {%0,%1,%2,%3};"
        : "+f"(c[0]), "+f"(c[1]), "+f"(c[2]), "+f"(c[3])
        : "r"(a[0]), "r"(a[1]), "r"(a[2]), "r"(a[3]), "r"(b[0]), "r"(b[1]));
}
__device__ __forceinline__ void ldsm4(uint32_t* r, uint32_t addr) {
    asm volatile("ldmatrix.sync.aligned.m8n8.x4.shared.b16 {%0,%1,%2,%3}, [%4];"
                 : "=r"(r[0]), "=r"(r[1]), "=r"(r[2]), "=r"(r[3]) : "r"(addr));
}
// fp16 tile (128B rows): 16B-granule XOR swizzle
__device__ __forceinline__ uint32_t swzH(int row, int col) {
    return (uint32_t)(row * 128 + (col ^ ((row & 7) << 4)));
}
// fp32 tile (256B rows): 32B-granule XOR swizzle
__device__ __forceinline__ uint32_t swzF(int row, int col) {
    return (uint32_t)(row * 256 + (col ^ ((row & 7) << 5)));
}
__device__ __forceinline__ uint32_t h2u(__half2 h) {
    union { __half2 h; uint32_t u; } c; c.h = h; return c.u;
}
__device__ __forceinline__ uint32_t f2h2(float a, float b) {
    return h2u(__floats2half2_rn(a, b));
}

// ============================================================================
// gemm1: WcT[m,n] = sum_k Wo[k,m] * Wv[n,k]   (fp32 in, fp16 out)
// BM=128 (m), BN=64 (n), BK=64.  8 warps: WM=2 (wm 64), WN=4 (wn 16).
// A-source tile: raw Wo rows  [64 k-rows x 128 m-cols] fp32, 528B padded rows.
// B-source tile: Wv rows      [64 n-rows x  64 k-cols] fp32, swzF.
// Bias CTAs (blockIdx.y == 8): t[j] = 2048*sum_i bv[i]*Wo[i,j] + bo[j].
// ============================================================================
#define G1T 256
constexpr uint32_t G1_AT  = 64u * 528u;          // 33792
constexpr uint32_t G1_BT  = 64u * 256u;          // 16384
constexpr uint32_t G1_STG = G1_AT + G1_BT;       // 50176
constexpr uint32_t SM_G1  = 2u * G1_STG;         // 100352

__global__ __launch_bounds__(G1T)
void gemm1_w(const float* __restrict__ Wo, const float* __restrict__ Wv,
             __half* __restrict__ WcT,
             const float* __restrict__ bv, const float* __restrict__ bo,
             float* __restrict__ tvec)
{
    const int tid = threadIdx.x;

    // ---- bias CTAs --------------------------------------------------------
    if (blockIdx.y == 8) {
        __shared__ float red[4][64];
        const int c = tid & 63, q = tid >> 6;
        const int j = blockIdx.x * 64 + c;
        const int i0 = q * 256;
        float s = 0.0f;
        #pragma unroll 16
        for (int i = 0; i < 256; i++)
            s = fmaf(bv[i0 + i], Wo[(size_t)(i0 + i) * 1024 + j], s);
        red[q][c] = s;
        __syncthreads();
        if (q == 0)
            tvec[j] = 2048.0f * (red[0][c] + red[1][c] +
                                 red[2][c] + red[3][c]) + bo[j];
        return;
    }

    // ---- GEMM CTAs --------------------------------------------------------
    extern __shared__ char smem[];
    const uint32_t sb = smem_u32(smem);
    const int wid = tid >> 5, lane = tid & 31;
    const int g = lane >> 2, tig = lane & 3;
    const int mb = blockIdx.y * 128;   // m base (Wo column)
    const int nb = blockIdx.x * 64;    // n base (Wv row)
    const int wm = (wid & 1) * 64;
    const int wn = (wid >> 1) * 16;

    float acc[4][2][4];
    #pragma unroll
    for (int mt = 0; mt < 4; mt++)
        #pragma unroll
        for (int nt = 0; nt < 2; nt++)
            #pragma unroll
            for (int i = 0; i < 4; i++) acc[mt][nt][i] = 0.0f;

    auto issue = [&](int c) {
        const int k0 = c * 64;
        const uint32_t stg = sb + (uint32_t)(c & 1) * G1_STG;
        // A: Wo[k0+r, mb + gc*4]  (64 rows x 32 granules)
        #pragma unroll
        for (int i = 0; i < 8; i++) {
            const int li = i * G1T + tid;
            const int r = li >> 5, gc = li & 31;
            cp_async16(stg + (uint32_t)(r * 528 + gc * 16),
                       Wo + (size_t)(k0 + r) * 1024 + mb + gc * 4);
        }
        // B: Wv[nb+r, k0 + gc*4]  (64 rows x 16 granules)
        #pragma unroll
        for (int i = 0; i < 4; i++) {
            const int li = i * G1T + tid;
            const int r = li >> 4, gc = li & 15;
            cp_async16(stg + G1_AT + swzF(r, gc * 16),
                       Wv + (size_t)(nb + r) * 1024 + k0 + gc * 4);
        }
        CP_COMMIT();
    };

    issue(0);

    for (int c = 0; c < 16; c++) {
        CP_WAIT0();
        __syncthreads();
        if (c + 1 < 16) issue(c + 1);

        const char* baseA = smem + (size_t)(c & 1) * G1_STG;
        const char* baseB = baseA + G1_AT;

        #pragma unroll
        for (int ks = 0; ks < 4; ks++) {
            const int ka = ks * 16 + tig * 2;
            uint32_t aF[4][4], bF[4];

            // A fragments: A[m,k] = tile[k - k0][m - mb] (scalar gather + cvt)
            #pragma unroll
            for (int mt = 0; mt < 4; mt++) {
                const int m0 = wm + mt * 16 + g, m1 = m0 + 8;
                const char* r0p = baseA + ka * 528;
                const char* r1p = r0p + 528;
                const char* r8p = r0p + 8 * 528;
                const char* r9p = r8p + 528;
                aF[mt][0] = f2h2(*(const float*)(r0p + m0 * 4),
                                 *(const float*)(r1p + m0 * 4));
                aF[mt][1] = f2h2(*(const float*)(r0p + m1 * 4),
                                 *(const float*)(r1p + m1 * 4));
                aF[mt][2] = f2h2(*(const float*)(r8p + m0 * 4),
                                 *(const float*)(r9p + m0 * 4));
                aF[mt][3] = f2h2(*(const float*)(r8p + m1 * 4),
                                 *(const float*)(r9p + m1 * 4));
            }
            // B fragments: B[n,k] from fp32 [N,K] tile (float2 + cvt)
            #pragma unroll
            for (int nt = 0; nt < 2; nt++) {
                const int row = wn + nt * 8 + g;
                const int cb = ka * 4;
                float2 lo = *(const float2*)(baseB + swzF(row, cb));
                float2 hi = *(const float2*)(baseB + swzF(row, cb + 32));
                bF[nt * 2 + 0] = f2h2(lo.x, lo.y);
                bF[nt * 2 + 1] = f2h2(hi.x, hi.y);
            }
            #pragma unroll
            for (int mt = 0; mt < 4; mt++) {
                mma16816(acc[mt][0], aF[mt], &bF[0]);
                mma16816(acc[mt][1], aF[mt], &bF[2]);
            }
        }
        __syncthreads();
    }

    // ---- epilogue: fp16 half2 stores to WcT
    #pragma unroll
    for (int mt = 0; mt < 4; mt++) {
        const size_t r0 = (size_t)mb + wm + mt * 16 + g;
        #pragma unroll
        for (int nt = 0; nt < 2; nt++) {
            const int c0 = nb + wn + nt * 8 + tig * 2;
            *(__half2*)(WcT + r0 * 1024 + c0) =
                __floats2half2_rn(acc[mt][nt][0], acc[mt][nt][1]);
            *(__half2*)(WcT + (r0 + 8) * 1024 + c0) =
                __floats2half2_rn(acc[mt][nt][2], acc[mt][nt][3]);
        }
    }
}

// ============================================================================
// gemm2: out[m,n] = 2048 * sum_k x[m,k] * WcT[n,k] + t[n]
// BM=64, BN=128, 4 warps (WM=2, WN=2): warp tile 32x64. MT=2, NT2=4.
// A = x fp32 (256B swzF rows, in-kernel cvt); B = WcT fp16 (swzH + ldmatrix).
// ============================================================================
#define G2T 128
constexpr uint32_t G2_AT  = 64u * 256u;          // 16384
constexpr uint32_t G2_BT  = 128u * 128u;         // 16384
constexpr uint32_t G2_STG = G2_AT + G2_BT;       // 32768
constexpr uint32_t SM_G2  = 2u * G2_STG;         // 65536

__global__ __launch_bounds__(G2T)
void gemm2_x(const float* __restrict__ x, const __half* __restrict__ B,
             float* __restrict__ C, const float* __restrict__ bias)
{
    extern __shared__ char smem[];
    const uint32_t sb = smem_u32(smem);
    const int tid = threadIdx.x;
    const int wid = tid >> 5, lane = tid & 31;
    const int g = lane >> 2, tig = lane & 3;
    const int bm = blockIdx.y, bn = blockIdx.x;
    const int wm = (wid & 1) * 32;
    const int wn = (wid >> 1) * 64;
    const int lm = lane >> 3, lr = lane & 7;
    const int N = 1024, K = 1024;

    const float* Ab = x + (size_t)bm * 64 * K;
    const __half* Bb = B + (size_t)bn * 128 * K;

    float acc[2][8][4];
    #pragma unroll
    for (int mt = 0; mt < 2; mt++)
        #pragma unroll
        for (int nt = 0; nt < 8; nt++)
            #pragma unroll
            for (int i = 0; i < 4; i++) acc[mt][nt][i] = 0.0f;

    auto issue = [&](int c) {
        const int k0 = c * 64;
        const uint32_t stg = sb + (uint32_t)(c & 1) * G2_STG;
        #pragma unroll
        for (int i = 0; i < 8; i++) {          // A: 64 rows x 16 granules
            const int li = i * G2T + tid;
            const int r = li >> 4, gc = li & 15;
            cp_async16(stg + swzF(r, gc * 16),
                       Ab + (size_t)r * K + k0 + gc * 4);
        }
        #pragma unroll
        for (int i = 0; i < 8; i++) {          // B: 128 rows x 8 granules
            const int li = i * G2T + tid;
            const int r = li >> 3, gc = li & 7;
            cp_async16(stg + G2_AT + swzH(r, gc * 16),
                       Bb + (size_t)r * K + k0 + gc * 8);
        }
        CP_COMMIT();
    };

    issue(0);

    for (int c = 0; c < 16; c++) {
        CP_WAIT0();
        __syncthreads();
        if (c + 1 < 16) issue(c + 1);

        const char* baseA = smem + (size_t)(c & 1) * G2_STG;
        const uint32_t tB = sb + (uint32_t)(c & 1) * G2_STG + G2_AT;

        #pragma unroll
        for (int ks = 0; ks < 4; ks++) {
            const int kb = ks * 32;                 // fp16-tile byte col
            uint32_t aF[2][4], bF[4][4];

            const int cb = ks * 64 + tig * 8;       // fp32-tile byte col
            #pragma unroll
            for (int mt = 0; mt < 2; mt++) {
                const int r0 = wm + mt * 16 + g, r1 = r0 + 8;
                float2 v00 = *(const float2*)(baseA + swzF(r0, cb));
                float2 v10 = *(const float2*)(baseA + swzF(r1, cb));
                float2 v01 = *(const float2*)(baseA + swzF(r0, cb + 32));
                float2 v11 = *(const float2*)(baseA + swzF(r1, cb + 32));
                aF[mt][0] = f2h2(v00.x, v00.y);
                aF[mt][1] = f2h2(v10.x, v10.y);
                aF[mt][2] = f2h2(v01.x, v01.y);
                aF[mt][3] = f2h2(v11.x, v11.y);
            }
            #pragma unroll
            for (int nt2 = 0; nt2 < 4; nt2++) {
                const int row = wn + (2 * nt2 + (lm >> 1)) * 8 + lr;
                ldsm4(bF[nt2], tB + swzH(row, kb + (lm & 1) * 16));
            }
            #pragma unroll
            for (int mt = 0; mt < 2; mt++)
                #pragma unroll
                for (int nt2 = 0; nt2 < 4; nt2++) {
                    mma16816(acc[mt][2 * nt2],     aF[mt], &bF[nt2][0]);
                    mma16816(acc[mt][2 * nt2 + 1], aF[mt], &bF[nt2][2]);
                }
        }
        __syncthreads();
    }

    // ---- epilogue
    #pragma unroll
    for (int mt = 0; mt < 2; mt++) {
        const size_t r0 = (size_t)bm * 64 + wm + mt * 16 + g;
        #pragma unroll
        for (int nt = 0; nt < 8; nt++) {
            const int c0 = bn * 128 + wn + nt * 8 + tig * 2;
            const float bx = bias[c0], by = bias[c0 + 1];
            *(float2*)(C + r0 * N + c0) =
                make_float2(2048.0f * acc[mt][nt][0] + bx,
                            2048.0f * acc[mt][nt][1] + by);
            *(float2*)(C + (r0 + 8) * N + c0) =
                make_float2(2048.0f * acc[mt][nt][2] + bx,
                            2048.0f * acc[mt][nt][3] + by);
        }
    }
}

// ---------------------------------------------------------------------------
extern "C" void kernel_launch(void* const* d_in, const int* in_sizes, int n_in,
                              void* d_out, int out_size)
{
    const float* x  = (const float*)d_in[0];
    // d_in[1..5] = encoder_x, Wq, bq, Wk, bk -- mathematically dead
    const float* Wv = (const float*)d_in[6];
    const float* bv = (const float*)d_in[7];
    const float* Wo = (const float*)d_in[8];
    const float* bo = (const float*)d_in[9];
    float* out = (float*)d_out;

    __half* WcTh;
    float* t;
    cudaGetSymbolAddress((void**)&WcTh, g_WcTh);
    cudaGetSymbolAddress((void**)&t,    g_t);

    static int smem_set = 0;
    if (!smem_set) {
        cudaFuncSetAttribute(gemm1_w,
                             cudaFuncAttributeMaxDynamicSharedMemorySize, SM_G1);
        cudaFuncSetAttribute(gemm2_x,
                             cudaFuncAttributeMaxDynamicSharedMemorySize, SM_G2);
        smem_set = 1;
    }

    // 1) gemm1: WcT = Wo^T @ Wv^T (128 CTAs) + 16 bias CTAs -> 144 CTAs
    {
        dim3 g(16, 9);   // y==8 -> bias CTAs
        gemm1_w<<<g, G1T, SM_G1>>>(Wo, Wv, WcTh, bv, bo, t);
    }

    // 2) gemm2: out = 2048 * x @ Wc + t  (1024 CTAs)
    {
        dim3 g(8, 128);
        gemm2_x<<<g, G2T, SM_G2>>>(x, WcTh, out, t);
    }
}